// round 16
// baseline (speedup 1.0000x reference)
#include <cuda_runtime.h>
#include <cuda_bf16.h>
#include <cstdint>

// LandmarksLoss: mean((pred - true)^2), true = windowed 128x128 bell table.
//
// R15: stream pred via TMA bulk copies (cp.async.bulk, engine-tracked) instead
// of per-warp LDG (MSHR-capped at ~19 B/cyc/SM across all prior variants).
// Per CTA (one image): 8 chunks of 28 rows (25088 B), double-buffered in smem
// with mbarrier expect_tx completion; compute reads p from smem (LDS) + bell
// via __ldg, R10 math otherwise. Deterministic fused last-block reduction.

#define H_DIM     224
#define W_DIM     224
#define HW        (H_DIM * W_DIM)      // 50176
#define ROWF4     (W_DIM / 4)          // 56
#define THREADS   256
#define NWARP     (THREADS / 32)
#define CH_ROWS   28
#define CH_F4     (CH_ROWS * ROWF4)    // 1568 float4 per chunk
#define CH_BYTES  (CH_F4 * 16)         // 25088
#define NCHUNK    (H_DIM / CH_ROWS)    // 8
#define MAX_BL    4096
#define DELTA     128
#define HALF      64

// dynamic smem: buf0[CH_F4] | buf1[CH_F4] | 2 mbarriers (16B)
#define SMEM_MBAR_OFF (2 * CH_BYTES)
#define SMEM_BYTES    (SMEM_MBAR_OFF + 32)

__device__ float        g_partials[MAX_BL];
__device__ unsigned int g_count = 0;

__device__ __forceinline__ uint32_t smem_u32(const void* p) {
    uint32_t a;
    asm("{ .reg .u64 t; cvta.to.shared.u64 t, %1; cvt.u32.u64 %0, t; }"
        : "=r"(a) : "l"(p));
    return a;
}

__device__ __forceinline__ void mbar_init(uint32_t a, uint32_t cnt) {
    asm volatile("mbarrier.init.shared.b64 [%0], %1;" :: "r"(a), "r"(cnt) : "memory");
}
__device__ __forceinline__ void mbar_expect(uint32_t a, uint32_t bytes) {
    asm volatile("mbarrier.arrive.expect_tx.shared.b64 _, [%0], %1;"
                 :: "r"(a), "r"(bytes) : "memory");
}
__device__ __forceinline__ void mbar_wait(uint32_t a, uint32_t parity) {
    asm volatile(
        "{\n\t"
        ".reg .pred P;\n\t"
        "WL_%=:\n\t"
        "mbarrier.try_wait.parity.acquire.cta.shared::cta.b64 P, [%0], %1, 0x989680;\n\t"
        "@P bra.uni WD_%=;\n\t"
        "bra.uni WL_%=;\n\t"
        "WD_%=:\n\t"
        "}"
        :: "r"(a), "r"(parity) : "memory");
}
__device__ __forceinline__ void bulk_g2s(uint32_t dst, const void* src,
                                         uint32_t bytes, uint32_t mbar) {
    asm volatile(
        "cp.async.bulk.shared::cta.global.mbarrier::complete_tx::bytes [%0], [%1], %2, [%3];"
        :: "r"(dst), "l"(src), "r"(bytes), "r"(mbar) : "memory");
}

__device__ __forceinline__ float blockReduce(float v, float* s)
{
    #pragma unroll
    for (int off = 16; off > 0; off >>= 1)
        v += __shfl_down_sync(0xFFFFFFFFu, v, off);
    const int lane = threadIdx.x & 31;
    const int wid  = threadIdx.x >> 5;
    if (lane == 0) s[wid] = v;
    __syncthreads();
    if (wid == 0) {
        v = (lane < NWARP) ? s[lane] : 0.0f;
        #pragma unroll
        for (int off = NWARP / 2; off > 0; off >>= 1)
            v += __shfl_down_sync(0xFFFFFFFFu, v, off);
    }
    return v;  // valid in thread 0
}

extern __shared__ float4 dynsmem[];

__global__ void __launch_bounds__(THREADS)
landmarks_fused(const float* __restrict__ pred,
                const float* __restrict__ lm,
                const float* __restrict__ bell,
                float* __restrict__ out,
                int n_bl, float inv_n)
{
    const int bl  = blockIdx.x;
    const int tid = threadIdx.x;
    const char* gsrc = reinterpret_cast<const char*>(pred) + (size_t)bl * HW * 4;

    const uint32_t smem_base = smem_u32(dynsmem);
    const uint32_t buf_addr[2] = { smem_base, smem_base + CH_BYTES };
    const uint32_t mbar[2]     = { smem_base + SMEM_MBAR_OFF,
                                   smem_base + SMEM_MBAR_OFF + 8 };
    const float4* buf[2] = { dynsmem, dynsmem + CH_F4 };

    if (tid == 0) {
        mbar_init(mbar[0], 1);
        mbar_init(mbar[1], 1);
    }
    __syncthreads();

    // landmarks: [...,0] = y_r, [...,1] = x_r  (round-half-to-even = jnp.round)
    const int yr = (int)rintf(__ldg(&lm[2 * bl + 0]));
    const int xr = (int)rintf(__ldg(&lm[2 * bl + 1]));
    const int xoff = HALF - xr;   // bell row = h + xoff
    const int yoff = HALF - yr;   // bell col = w + yoff

    // Prime the double buffer.
    if (tid == 0) {
        mbar_expect(mbar[0], CH_BYTES);
        bulk_g2s(buf_addr[0], gsrc, CH_BYTES, mbar[0]);
        mbar_expect(mbar[1], CH_BYTES);
        bulk_g2s(buf_addr[1], gsrc + CH_BYTES, CH_BYTES, mbar[1]);
    }

    float acc = 0.0f;
    int phase[2] = { 0, 0 };

    for (int c = 0; c < NCHUNK; ++c) {
        const int b = c & 1;
        mbar_wait(mbar[b], phase[b]);
        phase[b] ^= 1;

        const float4* p4 = buf[b];
        const int hbase = c * CH_ROWS;

        #pragma unroll 4
        for (int i = tid; i < CH_F4; i += THREADS) {
            const float4 p = p4[i];

            const int hl = i / ROWF4;
            const int w0 = (i - hl * ROWF4) * 4;

            const int ix = hbase + hl + xoff;
            const bool rowok = ((unsigned)ix < (unsigned)DELTA);
            const int iy0 = w0 + yoff;
            const float* brow = bell + ix * DELTA;

            float t0 = 0.0f, t1 = 0.0f, t2 = 0.0f, t3 = 0.0f;
            if (rowok) {
                if ((unsigned)(iy0 + 0) < (unsigned)DELTA) t0 = __ldg(&brow[iy0 + 0]);
                if ((unsigned)(iy0 + 1) < (unsigned)DELTA) t1 = __ldg(&brow[iy0 + 1]);
                if ((unsigned)(iy0 + 2) < (unsigned)DELTA) t2 = __ldg(&brow[iy0 + 2]);
                if ((unsigned)(iy0 + 3) < (unsigned)DELTA) t3 = __ldg(&brow[iy0 + 3]);
            }

            const float d0 = p.x - t0;
            const float d1 = p.y - t1;
            const float d2 = p.z - t2;
            const float d3 = p.w - t3;
            acc = fmaf(d0, d0, acc);
            acc = fmaf(d1, d1, acc);
            acc = fmaf(d2, d2, acc);
            acc = fmaf(d3, d3, acc);
        }

        __syncthreads();   // all threads done reading buf b
        if (c + 2 < NCHUNK && tid == 0) {
            mbar_expect(mbar[b], CH_BYTES);
            bulk_g2s(buf_addr[b], gsrc + (size_t)(c + 2) * CH_BYTES, CH_BYTES, mbar[b]);
        }
    }

    __shared__ float s[NWARP];
    const float bsum = blockReduce(acc, s);

    __shared__ bool amLast;
    if (tid == 0) {
        g_partials[bl] = bsum;
        __threadfence();
        const unsigned prev = atomicAdd(&g_count, 1u);
        amLast = (prev == (unsigned)(gridDim.x - 1));
    }
    __syncthreads();

    if (amLast) {
        // Deterministic final reduction: fixed index order every run.
        float tot = 0.0f;
        for (int i = tid; i < n_bl; i += THREADS)
            tot += __ldcg(&g_partials[i]);
        __syncthreads();   // reuse s[] safely
        const float t = blockReduce(tot, s);
        if (tid == 0) {
            out[0] = t * inv_n;
            g_count = 0;   // reset for next graph replay
        }
    }
}

extern "C" void kernel_launch(void* const* d_in, const int* in_sizes, int n_in,
                              void* d_out, int out_size)
{
    const float* pred = (const float*)d_in[0];  // (B, L, 224, 224)
    const float* lm   = (const float*)d_in[1];  // (B, L, 2)
    const float* bell = (const float*)d_in[2];  // (128, 128)
    float* out = (float*)d_out;

    const int n_bl = in_sizes[1] / 2;           // B*L = 1088
    const float inv_n = 1.0f / ((float)n_bl * (float)HW);

    static int smem_set = 0;
    if (!smem_set) {
        cudaFuncSetAttribute(landmarks_fused,
                             cudaFuncAttributeMaxDynamicSharedMemorySize,
                             SMEM_BYTES);
        smem_set = 1;
    }

    landmarks_fused<<<n_bl, THREADS, SMEM_BYTES>>>(pred, lm, bell, out, n_bl, inv_n);
}

// round 17
// speedup vs baseline: 1.1420x; 1.1420x over previous
#include <cuda_runtime.h>
#include <cuda_bf16.h>

// LandmarksLoss: mean((pred - true)^2), true = windowed 128x128 bell table.
//
// R17: R10 fused scheme with a lean fixed-column mapping: 224 threads/CTA,
// thread owns float4-column w4 = tid%56 and walks rows in steps of 4
// (56 iterations over the 224-row image). All column predicates and the bell
// column base are loop-invariant; per-iteration index work is one add + one
// compare. No payload batching (regs stay ~32 -> full occupancy, unlike R8).
// Deterministic fused last-block final reduction.

#define H_DIM     224
#define W_DIM     224
#define HW        (H_DIM * W_DIM)      // 50176
#define ROWF4     (W_DIM / 4)          // 56
#define NF4       (HW / 4)             // 12544
#define THREADS   224                  // 4 rows x 56 cols
#define NWARP     (THREADS / 32)       // 7
#define ROWSTEP   4                    // rows advanced per iteration
#define ITERS     (H_DIM / ROWSTEP)    // 56
#define MAX_BL    4096
#define DELTA     128
#define HALF      64

__device__ float        g_partials[MAX_BL];
__device__ unsigned int g_count = 0;

__device__ __forceinline__ float blockReduce(float v, float* s)
{
    #pragma unroll
    for (int off = 16; off > 0; off >>= 1)
        v += __shfl_down_sync(0xFFFFFFFFu, v, off);
    const int lane = threadIdx.x & 31;
    const int wid  = threadIdx.x >> 5;
    if (lane == 0) s[wid] = v;
    __syncthreads();
    if (wid == 0) {
        v = (lane < NWARP) ? s[lane] : 0.0f;
        #pragma unroll
        for (int off = 4; off > 0; off >>= 1)
            v += __shfl_down_sync(0xFFFFFFFFu, v, off);
    }
    return v;  // valid in thread 0
}

__global__ void __launch_bounds__(THREADS, 8)
landmarks_fused(const float* __restrict__ pred,
                const float* __restrict__ lm,
                const float* __restrict__ bell,
                float* __restrict__ out,
                int n_bl, float inv_n)
{
    const int bl  = blockIdx.x;
    const int tid = threadIdx.x;

    // Thread -> (starting row h0 in [0,4), fixed float4-column w4 in [0,56))
    const int h0 = tid / ROWF4;
    const int w4 = tid - h0 * ROWF4;

    const float4* img4 = reinterpret_cast<const float4*>(pred)
                       + (size_t)bl * NF4 + tid;        // == (h0*56 + w4) + ...

    // landmarks: [...,0] = y_r, [...,1] = x_r  (round-half-to-even = jnp.round)
    const int yr = (int)rintf(__ldg(&lm[2 * bl + 0]));
    const int xr = (int)rintf(__ldg(&lm[2 * bl + 1]));

    const int ixb = h0 + (HALF - xr);          // bell row for iter k: ixb + 4k
    const int iy0 = 4 * w4 + (HALF - yr);      // bell cols iy0..iy0+3 (fixed)

    // Loop-invariant column predicates.
    const bool c0 = ((unsigned)(iy0 + 0) < (unsigned)DELTA);
    const bool c1 = ((unsigned)(iy0 + 1) < (unsigned)DELTA);
    const bool c2 = ((unsigned)(iy0 + 2) < (unsigned)DELTA);
    const bool c3 = ((unsigned)(iy0 + 3) < (unsigned)DELTA);
    const float* bcol = bell + iy0;            // column base (row added per iter)

    float acc = 0.0f;

    #pragma unroll 4
    for (int k = 0; k < ITERS; ++k) {
        const float4 p = __ldg(img4 + k * (ROWSTEP * ROWF4));

        const int ix  = ixb + ROWSTEP * k;
        const bool rok = ((unsigned)ix < (unsigned)DELTA);
        const float* rb = bcol + (ix << 7);

        float t0 = 0.f, t1 = 0.f, t2 = 0.f, t3 = 0.f;
        if (rok) {
            if (c0) t0 = __ldg(rb + 0);
            if (c1) t1 = __ldg(rb + 1);
            if (c2) t2 = __ldg(rb + 2);
            if (c3) t3 = __ldg(rb + 3);
        }

        float d;
        d = p.x - t0; acc = fmaf(d, d, acc);
        d = p.y - t1; acc = fmaf(d, d, acc);
        d = p.z - t2; acc = fmaf(d, d, acc);
        d = p.w - t3; acc = fmaf(d, d, acc);
    }

    __shared__ float s[NWARP];
    const float bsum = blockReduce(acc, s);

    __shared__ bool amLast;
    if (tid == 0) {
        g_partials[bl] = bsum;
        __threadfence();
        const unsigned prev = atomicAdd(&g_count, 1u);
        amLast = (prev == (unsigned)(gridDim.x - 1));
    }
    __syncthreads();

    if (amLast) {
        // Deterministic final reduction: fixed index order every run.
        float tot = 0.0f;
        for (int i = tid; i < n_bl; i += THREADS)
            tot += __ldcg(&g_partials[i]);
        __syncthreads();   // reuse s[] safely
        const float t = blockReduce(tot, s);
        if (tid == 0) {
            out[0] = t * inv_n;
            g_count = 0;   // reset for next graph replay
        }
    }
}

extern "C" void kernel_launch(void* const* d_in, const int* in_sizes, int n_in,
                              void* d_out, int out_size)
{
    const float* pred = (const float*)d_in[0];  // (B, L, 224, 224)
    const float* lm   = (const float*)d_in[1];  // (B, L, 2)
    const float* bell = (const float*)d_in[2];  // (128, 128)
    float* out = (float*)d_out;

    const int n_bl = in_sizes[1] / 2;           // B*L = 1088
    const float inv_n = 1.0f / ((float)n_bl * (float)HW);

    landmarks_fused<<<n_bl, THREADS>>>(pred, lm, bell, out, n_bl, inv_n);
}